// round 7
// baseline (speedup 1.0000x reference)
#include <cuda_runtime.h>
#include <cuda_fp16.h>
#include <cstdint>
#include <cfloat>

// Problem constants: z (2,64,8,64,64), embedding (4096,64)
#define CH 64
#define SPA 32768
#define NTOK 65536
#define KCODE 4096
#define OUT_ELEMS 4194304
#define TAU 1.0f            // ~33 sigma of fp16 score error + idx-embed quantization

// kB smem offsets (bytes)
#define SM_T   0          // t tile: [64 ch][64 tok] dup-fp16x2 uint32  = 16KB
#define SM_E   16384      // e tiles: 2 x [64 ch][128 codes] fp16      = 32KB
#define SM_E2  49152      // e2: 2 x 128 floats                         = 1KB
#define SM_RED 50176      // reduce: [8 warps][64 tok][3] floats        = 6KB
#define SM_TOT 56320

typedef unsigned long long ull;

// -------- static device scratch (no cudaMalloc allowed) --------
__device__ float g_tT[CH * NTOK];                         // pre-conv out [c][n] fp32
__device__ __align__(16) uint32_t g_tpT[NTOK / 64][64][64];   // [grp][ch][tok] dup fp16x2
__device__ __align__(16) __half g_ebT[KCODE / 128][64][128];  // [chunk][ch][code] fp16
__device__ int   g_idx[NTOK];
__device__ float g_e2[KCODE];
__device__ float g_pe[KCODE * CH];                        // emb @ post_w^T + post_b
__device__ float g_part[256];
__device__ int   g_cntA, g_cntB;
__device__ int   g_listA[NTOK];
__device__ int   g_candA[NTOK];
__device__ int   g_listB[NTOK];

// -------- helpers --------
__device__ __forceinline__ uint32_t smem_u32(const void* p) {
    uint32_t a;
    asm("{ .reg .u64 t; cvta.to.shared.u64 t, %1; cvt.u32.u64 %0, t; }" : "=r"(a) : "l"(p));
    return a;
}
__device__ __forceinline__ void cpa16(uint32_t dst, const void* src) {
    asm volatile("cp.async.cg.shared.global [%0], [%1], 16;" :: "r"(dst), "l"(src) : "memory");
}
#define CP_COMMIT() asm volatile("cp.async.commit_group;" ::: "memory")
#define CP_WAIT0()  asm volatile("cp.async.wait_group 0;" ::: "memory")
#define CP_WAIT1()  asm volatile("cp.async.wait_group 1;" ::: "memory")

// embed code index into low 12 mantissa bits (quantization <= 0.0625 at score<256)
__device__ __forceinline__ float embf(float s, uint32_t k) {
    return __uint_as_float((__float_as_uint(s) & 0xFFFFF000u) | k);
}
// running top-3 (smallest) insert: 5 FMNMX (alu pipe, overlaps fma pipe)
__device__ __forceinline__ void ins3(float& b1, float& b2, float& b3, float e) {
    float m1 = fminf(b1, e);
    float x  = fmaxf(b1, e);
    float m2 = fminf(b2, x);
    float x2 = fmaxf(b2, x);
    b3 = fminf(b3, x2);
    b2 = m2;
    b1 = m1;
}
__device__ __forceinline__ __half2 ash2(uint32_t u) {
    return *reinterpret_cast<__half2*>(&u);
}

// ============================================================================
// kP: pe = emb @ post_w^T + post_b ; e2 ; transposed fp16 codebook g_ebT
// ============================================================================
__global__ void kP(const float* __restrict__ emb,
                   const float* __restrict__ post_w,
                   const float* __restrict__ post_b) {
    __shared__ float wsm[64 * 65];
    __shared__ float esm[64];
    __shared__ float wred[2];
    int tid = threadIdx.x;
    if (tid == 0 && blockIdx.x == 0) { g_cntA = 0; g_cntB = 0; }

    for (int i = tid; i < 4096; i += 64)
        wsm[(i >> 6) * 65 + (i & 63)] = post_w[i];
    float wb = post_b[tid];

    for (int kk = 0; kk < 16; kk++) {
        int k = blockIdx.x * 16 + kk;
        __syncthreads();
        float v = emb[k * 64 + tid];
        esm[tid] = v;
        __syncthreads();
        float acc = wb;
#pragma unroll
        for (int c = 0; c < 64; c++)
            acc = fmaf(esm[c], wsm[tid * 65 + c], acc);
        g_pe[k * 64 + tid] = acc;

        g_ebT[k >> 7][tid][k & 127] = __float2half(v);

        float sq = v * v;
#pragma unroll
        for (int off = 16; off; off >>= 1)
            sq += __shfl_xor_sync(0xffffffffu, sq, off);
        if ((tid & 31) == 0) wred[tid >> 5] = sq;
        __syncthreads();
        if (tid == 0) g_e2[k] = wred[0] + wred[1];
    }
}

// ============================================================================
// kA: pre-conv fp32 -> g_tT[c][n]; dup-fp16 -> g_tpT[grp][c][tok]
// ============================================================================
__global__ void __launch_bounds__(256) kA(const float* __restrict__ z,
                                          const float* __restrict__ pre_w,
                                          const float* __restrict__ pre_b) {
    __shared__ float wsm[4096];
    __shared__ float bsm[64];
    int tid = threadIdx.x;
    int n = blockIdx.x * 256 + tid;
    for (int i = tid; i < 4096; i += 256) wsm[i] = pre_w[i];
    if (tid < 64) bsm[tid] = pre_b[tid];

    int b = n >> 15;
    int s = n & 32767;
    const float* zp = z + (size_t)b * (CH * SPA) + s;
    float zr[64];
#pragma unroll
    for (int c = 0; c < 64; c++) zr[c] = zp[(size_t)c * SPA];
    __syncthreads();

    int grp = n >> 6;
    int tk = n & 63;
    for (int o = 0; o < 64; o++) {
        float acc = bsm[o];
#pragma unroll
        for (int c = 0; c < 64; c++)
            acc = fmaf(zr[c], wsm[o * 64 + c], acc);
        g_tT[(size_t)o * NTOK + n] = acc;
        uint32_t hb = (uint32_t)__half_as_ushort(__float2half(acc));
        g_tpT[grp][o][tk] = hb | (hb << 16);
    }
}

// ============================================================================
// kB: fp16 HFMA2 distance pass + fused top-3 argmin epilogue.
// 1024 CTAs x 256 thr; 64 tokens/CTA; 32 chunks of 128 codes double-buffered.
// Thread (q=warp, p=lane): tokens 2p,2p+1 x codes [q*16, q*16+16) per chunk.
// Two 32-channel fp16x2 accumulators per (token, code-pair), combined in fp32.
// ============================================================================
__global__ void __launch_bounds__(256) kB() {
    extern __shared__ __align__(16) char sm[];
    uint32_t smb = smem_u32(sm);
    int tid = threadIdx.x;
    int q = tid >> 5;
    int p = tid & 31;
    int grp = blockIdx.x;
    int n0 = grp * 64;

    // prologue: t tile + e chunk0 (group0), e chunk1 (group1)
    const char* tsrc = (const char*)g_tpT + (size_t)grp * 16384;
    const char* esrc = (const char*)g_ebT;
#pragma unroll
    for (int it = 0; it < 4; it++)
        cpa16(smb + SM_T + tid * 16 + it * 4096, tsrc + tid * 16 + it * 4096);
#pragma unroll
    for (int it = 0; it < 4; it++)
        cpa16(smb + SM_E + tid * 16 + it * 4096, esrc + tid * 16 + it * 4096);
    if (tid < 32) cpa16(smb + SM_E2 + tid * 16, (const char*)g_e2 + tid * 16);
    CP_COMMIT();
#pragma unroll
    for (int it = 0; it < 4; it++)
        cpa16(smb + SM_E + 16384 + tid * 16 + it * 4096, esrc + 16384 + tid * 16 + it * 4096);
    if (tid < 32) cpa16(smb + SM_E2 + 512 + tid * 16, (const char*)g_e2 + 512 + tid * 16);
    CP_COMMIT();

    float b1[2] = {FLT_MAX, FLT_MAX}, b2[2] = {FLT_MAX, FLT_MAX}, b3[2] = {FLT_MAX, FLT_MAX};

    for (int i = 0; i < 32; i++) {
        if (i < 31) { CP_WAIT1(); } else { CP_WAIT0(); }
        __syncthreads();
        int buf = i & 1;
        const char* eb = sm + SM_E + buf * 16384;
        const char* tb = sm + SM_T;

        __half2 acc[2][2][8];
#pragma unroll
        for (int h = 0; h < 2; h++) {
#pragma unroll
            for (int c = 0; c < 32; c++) {
                int ch = h * 32 + c;
                uint4 ea = *(const uint4*)(eb + ch * 256 + q * 32);
                uint4 e4 = *(const uint4*)(eb + ch * 256 + q * 32 + 16);
                ull tp = *(const ull*)(tb + ch * 256 + p * 8);
                __half2 t0 = ash2((uint32_t)tp);
                __half2 t1 = ash2((uint32_t)(tp >> 32));
                __half2 ev[8] = {ash2(ea.x), ash2(ea.y), ash2(ea.z), ash2(ea.w),
                                 ash2(e4.x), ash2(e4.y), ash2(e4.z), ash2(e4.w)};
                if (c == 0) {
#pragma unroll
                    for (int j = 0; j < 8; j++) {
                        acc[h][0][j] = __hmul2(t0, ev[j]);
                        acc[h][1][j] = __hmul2(t1, ev[j]);
                    }
                } else {
#pragma unroll
                    for (int j = 0; j < 8; j++) {
                        acc[h][0][j] = __hfma2(t0, ev[j], acc[h][0][j]);
                        acc[h][1][j] = __hfma2(t1, ev[j], acc[h][1][j]);
                    }
                }
            }
        }

        // epilogue: combine halves in fp32, score, insert into top-3
        int kb = i * 128 + q * 16;
        const float* e2b = (const float*)(sm + SM_E2 + buf * 512);
#pragma unroll
        for (int j = 0; j < 8; j++) {
            float2 e2p = *(const float2*)(e2b + q * 16 + 2 * j);
#pragma unroll
            for (int t = 0; t < 2; t++) {
                float lo = __low2float(acc[0][t][j])  + __low2float(acc[1][t][j]);
                float hi = __high2float(acc[0][t][j]) + __high2float(acc[1][t][j]);
                float s0 = fmaf(lo, -2.0f, e2p.x);
                float s1 = fmaf(hi, -2.0f, e2p.y);
                ins3(b1[t], b2[t], b3[t], embf(s0, (uint32_t)(kb + 2 * j)));
                ins3(b1[t], b2[t], b3[t], embf(s1, (uint32_t)(kb + 2 * j + 1)));
            }
        }

        __syncthreads();   // all warps done reading this e buffer
        if (i + 2 < 32) {
            const char* es = esrc + (size_t)(i + 2) * 16384;
#pragma unroll
            for (int it = 0; it < 4; it++)
                cpa16(smb + SM_E + buf * 16384 + tid * 16 + it * 4096, es + tid * 16 + it * 4096);
            if (tid < 32)
                cpa16(smb + SM_E2 + buf * 512 + tid * 16,
                      (const char*)g_e2 + (i + 2) * 512 + tid * 16);
            CP_COMMIT();
        }
    }

    // cross-warp merge of per-token top-3
    float* red = (float*)(sm + SM_RED);
#pragma unroll
    for (int t = 0; t < 2; t++) {
        int base = (q * 64 + 2 * p + t) * 3;
        red[base] = b1[t]; red[base + 1] = b2[t]; red[base + 2] = b3[t];
    }
    __syncthreads();
    if (tid < 64) {
        float c1 = FLT_MAX, c2 = FLT_MAX, c3 = FLT_MAX;
#pragma unroll
        for (int w = 0; w < 8; w++) {
            int base = (w * 64 + tid) * 3;
            ins3(c1, c2, c3, red[base]);
            ins3(c1, c2, c3, red[base + 1]);
            ins3(c1, c2, c3, red[base + 2]);
        }
        int n = n0 + tid;
        int i1 = (int)(__float_as_uint(c1) & 0xFFFu);
        g_idx[n] = i1;
        if (c2 - c1 < TAU) {
            if (c3 - c1 >= TAU) {
                int pos = atomicAdd(&g_cntA, 1);
                g_listA[pos] = n;
                g_candA[pos] = i1 | ((int)(__float_as_uint(c2) & 0xFFFu) << 16);
            } else {
                int pos = atomicAdd(&g_cntB, 1);
                g_listB[pos] = n;
            }
        }
    }
}

// ============================================================================
// kR1: exact fp32 2-candidate rescore
// ============================================================================
__global__ void __launch_bounds__(256) kR1(const float* __restrict__ emb) {
    int i = blockIdx.x * 256 + threadIdx.x;
    if (i >= g_cntA) return;
    int n = g_listA[i];
    int pk = g_candA[i];
    int i1 = pk & 0xFFFF;
    int i2 = (pk >> 16) & 0xFFFF;
    const float* e1 = emb + (size_t)i1 * 64;
    const float* e2v = emb + (size_t)i2 * 64;
    float d1 = 0.0f, d2 = 0.0f;
#pragma unroll
    for (int c = 0; c < 64; c++) {
        float t = g_tT[(size_t)c * NTOK + n];
        d1 = fmaf(t, e1[c], d1);
        d2 = fmaf(t, e2v[c], d2);
    }
    float s1 = fmaf(d1, -2.0f, g_e2[i1]);
    float s2 = fmaf(d2, -2.0f, g_e2[i2]);
    int best = (s2 < s1 || (s2 == s1 && i2 < i1)) ? i2 : i1;
    g_idx[n] = best;
}

// ============================================================================
// kR2: exact fp32 full-scan rescore of ambiguous tokens (8 per block)
// ============================================================================
__global__ void __launch_bounds__(256) kR2(const float* __restrict__ emb) {
    __shared__ float tv[8][64];
    __shared__ int tn[8];
    __shared__ float rv[256];
    __shared__ int ri[256];
    int tid = threadIdx.x;
    int cnt = g_cntB;
    int nblk = (cnt + 7) >> 3;

    for (int blk = blockIdx.x; blk < nblk; blk += gridDim.x) {
        int base = blk * 8;
        __syncthreads();
        if (tid < 8) tn[tid] = (base + tid < cnt) ? g_listB[base + tid] : -1;
        __syncthreads();
        for (int ii = tid; ii < 512; ii += 256) {
            int tt = ii >> 6, c = ii & 63;
            int n = (tn[tt] >= 0) ? tn[tt] : tn[0];
            tv[tt][c] = g_tT[(size_t)c * NTOK + n];
        }
        __syncthreads();

        float best[8];
        int bidx[8];
#pragma unroll
        for (int t = 0; t < 8; t++) { best[t] = FLT_MAX; bidx[t] = 0x7fffffff; }

        for (int c16 = 0; c16 < 16; c16++) {
            int k = c16 * 256 + tid;
            const float4* er = (const float4*)(emb + (size_t)k * 64);
            float d[8];
#pragma unroll
            for (int t = 0; t < 8; t++) d[t] = 0.0f;
#pragma unroll
            for (int c4 = 0; c4 < 16; c4++) {
                float4 ev = er[c4];
                int c = c4 * 4;
#pragma unroll
                for (int t = 0; t < 8; t++) {
                    d[t] = fmaf(tv[t][c + 0], ev.x, d[t]);
                    d[t] = fmaf(tv[t][c + 1], ev.y, d[t]);
                    d[t] = fmaf(tv[t][c + 2], ev.z, d[t]);
                    d[t] = fmaf(tv[t][c + 3], ev.w, d[t]);
                }
            }
            float e2k = g_e2[k];
#pragma unroll
            for (int t = 0; t < 8; t++) {
                float s = fmaf(d[t], -2.0f, e2k);
                if (s < best[t] || (s == best[t] && k < bidx[t])) { best[t] = s; bidx[t] = k; }
            }
        }

        for (int t = 0; t < 8; t++) {
            if (tn[t] < 0) break;
            rv[tid] = best[t];
            ri[tid] = bidx[t];
            __syncthreads();
#pragma unroll
            for (int st = 128; st > 0; st >>= 1) {
                if (tid < st) {
                    float v2 = rv[tid + st]; int j2 = ri[tid + st];
                    if (v2 < rv[tid] || (v2 == rv[tid] && j2 < ri[tid])) {
                        rv[tid] = v2; ri[tid] = j2;
                    }
                }
                __syncthreads();
            }
            if (tid == 0) g_idx[tn[t]] = ri[0];
            __syncthreads();
        }
    }
}

// ============================================================================
// kC: loss partials + post-conv (pe gather) + index output
// ============================================================================
__global__ void __launch_bounds__(256) kC(const float* __restrict__ emb,
                                          float* __restrict__ dout) {
    int tid = threadIdx.x;
    int n = blockIdx.x * 256 + tid;
    int idx = g_idx[n];

    const float4* er4 = (const float4*)(emb + (size_t)idx * 64);
    float lsum = 0.0f;
#pragma unroll
    for (int c4 = 0; c4 < 16; c4++) {
        float4 e4 = er4[c4];
        int c = c4 * 4;
        float d0 = e4.x - g_tT[(size_t)(c + 0) * NTOK + n];
        float d1 = e4.y - g_tT[(size_t)(c + 1) * NTOK + n];
        float d2 = e4.z - g_tT[(size_t)(c + 2) * NTOK + n];
        float d3 = e4.w - g_tT[(size_t)(c + 3) * NTOK + n];
        lsum = fmaf(d0, d0, lsum);
        lsum = fmaf(d1, d1, lsum);
        lsum = fmaf(d2, d2, lsum);
        lsum = fmaf(d3, d3, lsum);
    }

    int b = n >> 15;
    int s = n & 32767;
    float* op = dout + (size_t)b * (CH * SPA) + s;
    const float4* pr4 = (const float4*)(g_pe + (size_t)idx * 64);
#pragma unroll
    for (int o4 = 0; o4 < 16; o4++) {
        float4 pv = pr4[o4];
        int o = o4 * 4;
        op[(size_t)(o + 0) * SPA] = pv.x;
        op[(size_t)(o + 1) * SPA] = pv.y;
        op[(size_t)(o + 2) * SPA] = pv.z;
        op[(size_t)(o + 3) * SPA] = pv.w;
    }

    dout[OUT_ELEMS + 2 + n] = (float)idx;

    __shared__ float red[256];
    red[tid] = lsum;
    __syncthreads();
#pragma unroll
    for (int st = 128; st > 0; st >>= 1) {
        if (tid < st) red[tid] += red[tid + st];
        __syncthreads();
    }
    if (tid == 0) g_part[blockIdx.x] = red[0];
}

// ============================================================================
__global__ void kD(float* __restrict__ dout) {
    __shared__ float red[256];
    int tid = threadIdx.x;
    red[tid] = g_part[tid];
    __syncthreads();
#pragma unroll
    for (int st = 128; st > 0; st >>= 1) {
        if (tid < st) red[tid] += red[tid + st];
        __syncthreads();
    }
    if (tid == 0) {
        float m = red[0] / (float)OUT_ELEMS;
        dout[OUT_ELEMS]     = m;   // codebook_loss
        dout[OUT_ELEMS + 1] = m;   // commitment_loss (same forward value)
    }
}

// ============================================================================
extern "C" void kernel_launch(void* const* d_in, const int* in_sizes, int n_in,
                              void* d_out, int out_size) {
    const float* z      = (const float*)d_in[0];
    const float* emb    = (const float*)d_in[1];
    const float* pre_w  = (const float*)d_in[2];
    const float* pre_b  = (const float*)d_in[3];
    const float* post_w = (const float*)d_in[4];
    const float* post_b = (const float*)d_in[5];
    float* dout = (float*)d_out;

    cudaFuncSetAttribute(kB, cudaFuncAttributeMaxDynamicSharedMemorySize, SM_TOT);

    kP<<<KCODE / 16, 64>>>(emb, post_w, post_b);
    kA<<<NTOK / 256, 256>>>(z, pre_w, pre_b);
    kB<<<NTOK / 64, 256, SM_TOT>>>();
    kR1<<<NTOK / 256, 256>>>(emb);
    kR2<<<128, 256>>>(emb);
    kC<<<NTOK / 256, 256>>>(emb, dout);
    kD<<<1, 256>>>(dout);
}

// round 8
// speedup vs baseline: 1.3124x; 1.3124x over previous
#include <cuda_runtime.h>
#include <cstdint>
#include <cfloat>

// Problem constants: z (2,64,8,64,64), embedding (4096,64)
#define CH 64
#define SPA 32768
#define NTOK 65536
#define KCODE 4096
#define OUT_ELEMS 4194304
#define TAU 3.0f            // certify margin: ~19 sigma of int8 quant error + embed quantum

typedef unsigned long long ull;

// -------- static device scratch (no cudaMalloc allowed) --------
__device__ float g_tT[CH * NTOK];                        // pre-conv out [c][n] fp32 (exact)
__device__ __align__(16) uint32_t g_t8[NTOK][16];        // token int8x4 packed, 64B/row
__device__ float g_tA[NTOK];                             // -2*mt/127 per token
__device__ __align__(16) uint32_t g_e8[KCODE][16];       // code int8x4 packed
__device__ __align__(16) float2 g_eC[KCODE];             // (me/127, e2) per code
__device__ int   g_idx[NTOK];
__device__ float g_e2[KCODE];
__device__ float g_pe[KCODE * CH];                       // emb @ post_w^T + post_b
__device__ float g_part[256];
__device__ int   g_cntA, g_cntB;
__device__ int   g_listA[NTOK];
__device__ short g_cand6[NTOK * 6];
__device__ int   g_listB[NTOK];

// -------- helpers --------
__device__ __forceinline__ uint32_t smem_u32(const void* p) {
    uint32_t a;
    asm("{ .reg .u64 t; cvta.to.shared.u64 t, %1; cvt.u32.u64 %0, t; }" : "=r"(a) : "l"(p));
    return a;
}
__device__ __forceinline__ void cpa16(uint32_t dst, const void* src) {
    asm volatile("cp.async.cg.shared.global [%0], [%1], 16;" :: "r"(dst), "l"(src) : "memory");
}
#define CP_COMMIT() asm volatile("cp.async.commit_group;" ::: "memory")
#define CP_WAIT0()  asm volatile("cp.async.wait_group 0;" ::: "memory")
#define CP_WAIT1()  asm volatile("cp.async.wait_group 1;" ::: "memory")

__device__ __forceinline__ int dp4a(uint32_t a, uint32_t b, int c) {
    int d;
    asm("dp4a.s32.s32 %0, %1, %2, %3;" : "=r"(d) : "r"(a), "r"(b), "r"(c));
    return d;
}
// embed code index into low 12 mantissa bits (quantum <= 0.125 at score < 256)
__device__ __forceinline__ float embf(float s, uint32_t k) {
    return __uint_as_float((__float_as_uint(s) & 0xFFFFF000u) | k);
}
// sorted top-6 insert: 11 FMNMX on the alu pipe
__device__ __forceinline__ void ins6(float* b, float e) {
    float m, x;
    m = fminf(b[0], e); x = fmaxf(b[0], e); b[0] = m;
    m = fminf(b[1], x); x = fmaxf(b[1], x); b[1] = m;
    m = fminf(b[2], x); x = fmaxf(b[2], x); b[2] = m;
    m = fminf(b[3], x); x = fmaxf(b[3], x); b[3] = m;
    m = fminf(b[4], x); x = fmaxf(b[4], x); b[4] = m;
    b[5] = fminf(b[5], x);
}

// ============================================================================
// kP: pe = emb @ post_w^T + post_b ; e2 ; int8-quantized codebook + scales
// ============================================================================
__global__ void kP(const float* __restrict__ emb,
                   const float* __restrict__ post_w,
                   const float* __restrict__ post_b) {
    __shared__ float wsm[64 * 65];
    __shared__ float esm[64];
    __shared__ float wred[2];
    __shared__ float wredm[2];
    __shared__ char  sq8[64];
    int tid = threadIdx.x;
    if (tid == 0 && blockIdx.x == 0) { g_cntA = 0; g_cntB = 0; }

    for (int i = tid; i < 4096; i += 64)
        wsm[(i >> 6) * 65 + (i & 63)] = post_w[i];
    float wb = post_b[tid];

    for (int kk = 0; kk < 16; kk++) {
        int k = blockIdx.x * 16 + kk;
        __syncthreads();
        float v = emb[k * 64 + tid];
        esm[tid] = v;

        float sq = v * v;
        float mA = fabsf(v);
#pragma unroll
        for (int off = 16; off; off >>= 1) {
            sq += __shfl_xor_sync(0xffffffffu, sq, off);
            mA = fmaxf(mA, __shfl_xor_sync(0xffffffffu, mA, off));
        }
        if ((tid & 31) == 0) { wred[tid >> 5] = sq; wredm[tid >> 5] = mA; }
        __syncthreads();
        float e2k = wred[0] + wred[1];
        float mek = fmaxf(fmaxf(wredm[0], wredm[1]), 1e-30f);
        if (tid == 0) {
            g_e2[k] = e2k;
            g_eC[k] = make_float2(mek * (1.0f / 127.0f), e2k);
        }

        float acc = wb;
#pragma unroll
        for (int c = 0; c < 64; c++)
            acc = fmaf(esm[c], wsm[tid * 65 + c], acc);
        g_pe[k * 64 + tid] = acc;

        int q = __float2int_rn(v * (127.0f / mek));
        sq8[tid] = (char)q;
        __syncthreads();
        if (tid < 16) {
            uint32_t w = ((uint32_t)(uint8_t)sq8[4 * tid])
                       | ((uint32_t)(uint8_t)sq8[4 * tid + 1] << 8)
                       | ((uint32_t)(uint8_t)sq8[4 * tid + 2] << 16)
                       | ((uint32_t)(uint8_t)sq8[4 * tid + 3] << 24);
            g_e8[k][tid] = w;
        }
    }
}

// ============================================================================
// kA: pre-conv fp32 -> g_tT[c][n] (exact); int8 quantize -> g_t8, g_tA
// ============================================================================
__global__ void __launch_bounds__(256) kA(const float* __restrict__ z,
                                          const float* __restrict__ pre_w,
                                          const float* __restrict__ pre_b) {
    __shared__ float wsm[4096];
    __shared__ float bsm[64];
    int tid = threadIdx.x;
    int n = blockIdx.x * 256 + tid;
    for (int i = tid; i < 4096; i += 256) wsm[i] = pre_w[i];
    if (tid < 64) bsm[tid] = pre_b[tid];

    int b = n >> 15;
    int s = n & 32767;
    const float* zp = z + (size_t)b * (CH * SPA) + s;
    float zr[64];
#pragma unroll
    for (int c = 0; c < 64; c++) zr[c] = zp[(size_t)c * SPA];
    __syncthreads();

    float tl[64];
    float mt = 1e-30f;
    for (int o = 0; o < 64; o++) {
        float acc = bsm[o];
#pragma unroll
        for (int c = 0; c < 64; c++)
            acc = fmaf(zr[c], wsm[o * 64 + c], acc);
        g_tT[(size_t)o * NTOK + n] = acc;
        tl[o] = acc;
        mt = fmaxf(mt, fabsf(acc));
    }
    float scl = 127.0f / mt;
#pragma unroll
    for (int w = 0; w < 16; w++) {
        int q0 = __float2int_rn(tl[4 * w] * scl);
        int q1 = __float2int_rn(tl[4 * w + 1] * scl);
        int q2 = __float2int_rn(tl[4 * w + 2] * scl);
        int q3 = __float2int_rn(tl[4 * w + 3] * scl);
        g_t8[n][w] = ((uint32_t)(uint8_t)(char)q0)
                   | ((uint32_t)(uint8_t)(char)q1 << 8)
                   | ((uint32_t)(uint8_t)(char)q2 << 16)
                   | ((uint32_t)(uint8_t)(char)q3 << 24);
    }
    g_tA[n] = -2.0f * mt * (1.0f / 127.0f);
}

// ============================================================================
// kB: int8 dp4a distance screen + fused top-6 argmin (embedded indices).
// 256 CTAs x 256 thr; 1 token/thread; 32 chunks of 128 codes double-buffered.
// score~ = e2 - 2*(dotq)*(mt/127)*(me/127); exact-rescore tiers via TAU.
// ============================================================================
__global__ void __launch_bounds__(256) kB() {
    __shared__ __align__(16) uint32_t se[2][128][16];   // 16KB
    __shared__ __align__(16) float2  seC[2][128];       // 2KB: (me/127, e2)
    uint32_t smb_e = smem_u32(&se[0][0][0]);
    uint32_t smb_c = smem_u32(&seC[0][0]);

    int tid = threadIdx.x;
    int n = blockIdx.x * 256 + tid;

    // token registers
    uint32_t tq[16];
    {
        const uint4* tp = (const uint4*)&g_t8[n][0];
#pragma unroll
        for (int j = 0; j < 4; j++) {
            uint4 v = tp[j];
            tq[4 * j] = v.x; tq[4 * j + 1] = v.y; tq[4 * j + 2] = v.z; tq[4 * j + 3] = v.w;
        }
    }
    float tA = g_tA[n];

    // prologue: chunk0 (group0), chunk1 (group1)
    {
        const char* e0 = (const char*)&g_e8[0][0];
        cpa16(smb_e + tid * 16, e0 + tid * 16);
        cpa16(smb_e + 4096 + tid * 16, e0 + 4096 + tid * 16);
        if (tid < 64) cpa16(smb_c + tid * 16, (const char*)g_eC + tid * 16);
        CP_COMMIT();
        cpa16(smb_e + 8192 + tid * 16, e0 + 8192 + tid * 16);
        cpa16(smb_e + 12288 + tid * 16, e0 + 12288 + tid * 16);
        if (tid < 64) cpa16(smb_c + 1024 + tid * 16, (const char*)g_eC + 1024 + tid * 16);
        CP_COMMIT();
    }

    float bst[6] = {FLT_MAX, FLT_MAX, FLT_MAX, FLT_MAX, FLT_MAX, FLT_MAX};

    for (int i = 0; i < 32; i++) {
        if (i < 31) { CP_WAIT1(); } else { CP_WAIT0(); }
        __syncthreads();
        int buf = i & 1;
        int kb = i * 128;

#pragma unroll 4
        for (int k = 0; k < 128; k++) {
            const uint32_t* ew = se[buf][k];
            int acc = 0;
#pragma unroll
            for (int w = 0; w < 16; w++) acc = dp4a(tq[w], ew[w], acc);
            float2 c = seC[buf][k];
            float s = fmaf((float)acc * c.x, tA, c.y);
            ins6(bst, embf(s, (uint32_t)(kb + k)));
        }

        __syncthreads();
        if (i + 2 < 32) {
            const char* es = (const char*)&g_e8[(i + 2) * 128][0];
            cpa16(smb_e + buf * 8192 + tid * 16, es + tid * 16);
            cpa16(smb_e + buf * 8192 + 4096 + tid * 16, es + 4096 + tid * 16);
            if (tid < 64)
                cpa16(smb_c + buf * 1024 + tid * 16,
                      (const char*)(g_eC + (i + 2) * 128) + tid * 16);
            CP_COMMIT();
        }
    }

    int i1 = (int)(__float_as_uint(bst[0]) & 0xFFFu);
    g_idx[n] = i1;
    if (bst[1] - bst[0] < TAU) {
        if (bst[5] - bst[0] >= TAU) {
            int pos = atomicAdd(&g_cntA, 1);
            g_listA[pos] = n;
#pragma unroll
            for (int j = 0; j < 6; j++)
                g_cand6[pos * 6 + j] = (short)(__float_as_uint(bst[j]) & 0xFFFu);
        } else {
            int pos = atomicAdd(&g_cntB, 1);
            g_listB[pos] = n;
        }
    }
}

// ============================================================================
// kR6: exact fp32 rescore of 6 candidates (A-tier tokens)
// ============================================================================
__global__ void __launch_bounds__(256) kR6(const float* __restrict__ emb) {
    int i = blockIdx.x * 256 + threadIdx.x;
    if (i >= g_cntA) return;
    int n = g_listA[i];
    float tv[64];
#pragma unroll
    for (int c = 0; c < 64; c++) tv[c] = g_tT[(size_t)c * NTOK + n];
    float best = FLT_MAX;
    int bk = 0x7fffffff;
#pragma unroll
    for (int j = 0; j < 6; j++) {
        int k = (int)g_cand6[i * 6 + j];
        const float* er = emb + (size_t)k * 64;
        float dot = 0.0f;
#pragma unroll
        for (int c = 0; c < 64; c++) dot = fmaf(tv[c], er[c], dot);
        float s = fmaf(dot, -2.0f, g_e2[k]);
        if (s < best || (s == best && k < bk)) { best = s; bk = k; }
    }
    g_idx[n] = bk;
}

// ============================================================================
// kR2: exact fp32 full-scan rescore of ambiguous tokens (8 per block) — proven
// ============================================================================
__global__ void __launch_bounds__(256) kR2(const float* __restrict__ emb) {
    __shared__ float tv[8][64];
    __shared__ int tn[8];
    __shared__ float rv[256];
    __shared__ int ri[256];
    int tid = threadIdx.x;
    int cnt = g_cntB;
    int nblk = (cnt + 7) >> 3;

    for (int blk = blockIdx.x; blk < nblk; blk += gridDim.x) {
        int base = blk * 8;
        __syncthreads();
        if (tid < 8) tn[tid] = (base + tid < cnt) ? g_listB[base + tid] : -1;
        __syncthreads();
        for (int ii = tid; ii < 512; ii += 256) {
            int tt = ii >> 6, c = ii & 63;
            int n = (tn[tt] >= 0) ? tn[tt] : tn[0];
            tv[tt][c] = g_tT[(size_t)c * NTOK + n];
        }
        __syncthreads();

        float best[8];
        int bidx[8];
#pragma unroll
        for (int t = 0; t < 8; t++) { best[t] = FLT_MAX; bidx[t] = 0x7fffffff; }

        for (int c16 = 0; c16 < 16; c16++) {
            int k = c16 * 256 + tid;
            const float4* er = (const float4*)(emb + (size_t)k * 64);
            float d[8];
#pragma unroll
            for (int t = 0; t < 8; t++) d[t] = 0.0f;
#pragma unroll
            for (int c4 = 0; c4 < 16; c4++) {
                float4 ev = er[c4];
                int c = c4 * 4;
#pragma unroll
                for (int t = 0; t < 8; t++) {
                    d[t] = fmaf(tv[t][c + 0], ev.x, d[t]);
                    d[t] = fmaf(tv[t][c + 1], ev.y, d[t]);
                    d[t] = fmaf(tv[t][c + 2], ev.z, d[t]);
                    d[t] = fmaf(tv[t][c + 3], ev.w, d[t]);
                }
            }
            float e2k = g_e2[k];
#pragma unroll
            for (int t = 0; t < 8; t++) {
                float s = fmaf(d[t], -2.0f, e2k);
                if (s < best[t] || (s == best[t] && k < bidx[t])) { best[t] = s; bidx[t] = k; }
            }
        }

        for (int t = 0; t < 8; t++) {
            if (tn[t] < 0) break;
            rv[tid] = best[t];
            ri[tid] = bidx[t];
            __syncthreads();
#pragma unroll
            for (int st = 128; st > 0; st >>= 1) {
                if (tid < st) {
                    float v2 = rv[tid + st]; int j2 = ri[tid + st];
                    if (v2 < rv[tid] || (v2 == rv[tid] && j2 < ri[tid])) {
                        rv[tid] = v2; ri[tid] = j2;
                    }
                }
                __syncthreads();
            }
            if (tid == 0) g_idx[tn[t]] = ri[0];
            __syncthreads();
        }
    }
}

// ============================================================================
// kC: loss partials + post-conv (pe gather) + index output — proven
// ============================================================================
__global__ void __launch_bounds__(256) kC(const float* __restrict__ emb,
                                          float* __restrict__ dout) {
    int tid = threadIdx.x;
    int n = blockIdx.x * 256 + tid;
    int idx = g_idx[n];

    const float4* er4 = (const float4*)(emb + (size_t)idx * 64);
    float lsum = 0.0f;
#pragma unroll
    for (int c4 = 0; c4 < 16; c4++) {
        float4 e4 = er4[c4];
        int c = c4 * 4;
        float d0 = e4.x - g_tT[(size_t)(c + 0) * NTOK + n];
        float d1 = e4.y - g_tT[(size_t)(c + 1) * NTOK + n];
        float d2 = e4.z - g_tT[(size_t)(c + 2) * NTOK + n];
        float d3 = e4.w - g_tT[(size_t)(c + 3) * NTOK + n];
        lsum = fmaf(d0, d0, lsum);
        lsum = fmaf(d1, d1, lsum);
        lsum = fmaf(d2, d2, lsum);
        lsum = fmaf(d3, d3, lsum);
    }

    int b = n >> 15;
    int s = n & 32767;
    float* op = dout + (size_t)b * (CH * SPA) + s;
    const float4* pr4 = (const float4*)(g_pe + (size_t)idx * 64);
#pragma unroll
    for (int o4 = 0; o4 < 16; o4++) {
        float4 pv = pr4[o4];
        int o = o4 * 4;
        op[(size_t)(o + 0) * SPA] = pv.x;
        op[(size_t)(o + 1) * SPA] = pv.y;
        op[(size_t)(o + 2) * SPA] = pv.z;
        op[(size_t)(o + 3) * SPA] = pv.w;
    }

    dout[OUT_ELEMS + 2 + n] = (float)idx;

    __shared__ float red[256];
    red[tid] = lsum;
    __syncthreads();
#pragma unroll
    for (int st = 128; st > 0; st >>= 1) {
        if (tid < st) red[tid] += red[tid + st];
        __syncthreads();
    }
    if (tid == 0) g_part[blockIdx.x] = red[0];
}

// ============================================================================
__global__ void kD(float* __restrict__ dout) {
    __shared__ float red[256];
    int tid = threadIdx.x;
    red[tid] = g_part[tid];
    __syncthreads();
#pragma unroll
    for (int st = 128; st > 0; st >>= 1) {
        if (tid < st) red[tid] += red[tid + st];
        __syncthreads();
    }
    if (tid == 0) {
        float m = red[0] / (float)OUT_ELEMS;
        dout[OUT_ELEMS]     = m;   // codebook_loss
        dout[OUT_ELEMS + 1] = m;   // commitment_loss (same forward value)
    }
}

// ============================================================================
extern "C" void kernel_launch(void* const* d_in, const int* in_sizes, int n_in,
                              void* d_out, int out_size) {
    const float* z      = (const float*)d_in[0];
    const float* emb    = (const float*)d_in[1];
    const float* pre_w  = (const float*)d_in[2];
    const float* pre_b  = (const float*)d_in[3];
    const float* post_w = (const float*)d_in[4];
    const float* post_b = (const float*)d_in[5];
    float* dout = (float*)d_out;

    kP<<<KCODE / 16, 64>>>(emb, post_w, post_b);
    kA<<<NTOK / 256, 256>>>(z, pre_w, pre_b);
    kB<<<NTOK / 256, 256>>>();
    kR6<<<NTOK / 256, 256>>>(emb);
    kR2<<<128, 256>>>(emb);
    kC<<<NTOK / 256, 256>>>(emb, dout);
    kD<<<1, 256>>>(dout);
}

// round 9
// speedup vs baseline: 2.5074x; 1.9106x over previous
#include <cuda_runtime.h>
#include <cstdint>
#include <cfloat>

// Problem constants: z (2,64,8,64,64), embedding (4096,64)
#define CH 64
#define SPA 32768
#define NTOK 65536
#define KCODE 4096
#define OUT_ELEMS 4194304
#define TBLK 32
#define NBLK (NTOK / TBLK)      // 2048

// kB smem byte offsets (all 16B-aligned)
#define OFF_WSM  0              // pre_w [o][c] 4096 f          = 16384
#define OFF_BSM  16384          // pre_b 64 f                   = 256
#define OFF_ZSM  16640          // z tile [64 c][32 tok] f      = 8192
#define OFF_ESM  24832          // e chunks 2 x [64 c][128 k] f = 65536
#define OFF_TSM  90368          // t tile [64 c][32 tok] f      = 8192
#define OFF_E2   98560          // e2 2 x 128 f                 = 1024
#define OFF_RV   99584          // argmin vals [8 w][32 t] f    = 1024
#define OFF_RI   100608         // argmin idxs [8 w][32 t] i    = 1024
#define OFF_IDX  101632         // final idx [32] i             = 128
#define OFF_LSM  101760         // loss partials [8 w][32 t] f  = 1024
#define SMTOT    102784         // forces exactly 2 CTAs/SM (3x > 228KB)

typedef unsigned long long ull;

// -------- static device scratch (no cudaMalloc allowed) --------
__device__ __align__(16) float g_eT[KCODE / 128][64][128];   // [chunk][c][k] transposed emb
__device__ __align__(16) float g_e2[KCODE];
__device__ __align__(16) float g_pe[KCODE * CH];             // emb @ post_w^T + post_b
__device__ float g_part[NBLK];

// -------- helpers (proven in R2) --------
__device__ __forceinline__ uint32_t smem_u32(const void* p) {
    uint32_t a;
    asm("{ .reg .u64 t; cvta.to.shared.u64 t, %1; cvt.u32.u64 %0, t; }" : "=r"(a) : "l"(p));
    return a;
}
__device__ __forceinline__ void cpa16(uint32_t dst, const void* src) {
    asm volatile("cp.async.cg.shared.global [%0], [%1], 16;" :: "r"(dst), "l"(src) : "memory");
}
#define CP_COMMIT() asm volatile("cp.async.commit_group;" ::: "memory")
#define CP_WAIT0()  asm volatile("cp.async.wait_group 0;" ::: "memory")
#define CP_WAIT1()  asm volatile("cp.async.wait_group 1;" ::: "memory")

__device__ __forceinline__ ull ffma2(ull a, ull b, ull c) {
    ull d;
    asm("fma.rn.f32x2 %0, %1, %2, %3;" : "=l"(d) : "l"(a), "l"(b), "l"(c));
    return d;
}
__device__ __forceinline__ ull dup2(float x) {
    ull d;
    unsigned u = __float_as_uint(x);
    asm("mov.b64 %0, {%1, %2};" : "=l"(d) : "r"(u), "r"(u));
    return d;
}
__device__ __forceinline__ float f2lo(ull v) { return __uint_as_float((unsigned)v); }
__device__ __forceinline__ float f2hi(ull v) { return __uint_as_float((unsigned)(v >> 32)); }

// ============================================================================
// kP: pe = emb @ post_w^T + post_b ; e2 ; transposed fp32 codebook g_eT
// ============================================================================
__global__ void kP(const float* __restrict__ emb,
                   const float* __restrict__ post_w,
                   const float* __restrict__ post_b) {
    __shared__ float wsm[64 * 65];
    __shared__ float esm[64];
    __shared__ float wred[2];
    int tid = threadIdx.x;

    for (int i = tid; i < 4096; i += 64)
        wsm[(i >> 6) * 65 + (i & 63)] = post_w[i];
    float wb = post_b[tid];

    for (int kk = 0; kk < 16; kk++) {
        int k = blockIdx.x * 16 + kk;
        __syncthreads();
        float v = emb[k * 64 + tid];
        esm[tid] = v;
        __syncthreads();
        float acc = wb;
#pragma unroll
        for (int c = 0; c < 64; c++)
            acc = fmaf(esm[c], wsm[tid * 65 + c], acc);
        g_pe[k * 64 + tid] = acc;

        g_eT[k >> 7][tid][k & 127] = v;    // transposed chunk-major codebook

        float sq = v * v;
#pragma unroll
        for (int off = 16; off; off >>= 1)
            sq += __shfl_xor_sync(0xffffffffu, sq, off);
        if ((tid & 31) == 0) wred[tid >> 5] = sq;
        __syncthreads();
        if (tid == 0) g_e2[k] = wred[0] + wred[1];
    }
}

// ============================================================================
// kB: fused pre-conv + exact fp32 FFMA2 argmin + loss/gather/output epilogue.
// 2048 CTAs x 256 thr; 32 tokens/CTA (1/lane); warp q = 16-code stripe.
// e-chunk double-buffered cp.async (32 chunks of 128 codes).
// ============================================================================
__global__ void __launch_bounds__(256) kB(const float* __restrict__ z,
                                          const float* __restrict__ emb,
                                          const float* __restrict__ pre_w,
                                          const float* __restrict__ pre_b,
                                          float* __restrict__ dout) {
    extern __shared__ __align__(16) char sm[];
    uint32_t smb = smem_u32(sm);
    float* wsm  = (float*)(sm + OFF_WSM);
    float* bsm  = (float*)(sm + OFF_BSM);
    float* zsm  = (float*)(sm + OFF_ZSM);
    float* tsm  = (float*)(sm + OFF_TSM);
    float* rv   = (float*)(sm + OFF_RV);
    int*   ri   = (int*)  (sm + OFF_RI);
    int*   idxs = (int*)  (sm + OFF_IDX);
    float* lsm  = (float*)(sm + OFF_LSM);

    int tid = threadIdx.x;
    int q = tid >> 5;               // warp 0..7
    int p = tid & 31;               // lane = token within block
    int n0 = blockIdx.x * TBLK;
    int b  = n0 >> 15;
    int s0 = n0 & 32767;

    // ---- prologue: group A = {pre_w, pre_b, z tile, e chunk0, e2_0}; B = {chunk1, e2_1}
    const char* zb = (const char*)z + ((size_t)b * (CH * SPA) + s0) * 4;
#pragma unroll
    for (int it = 0; it < 4; it++)
        cpa16(smb + OFF_WSM + (tid + it * 256) * 16, (const char*)pre_w + (tid + it * 256) * 16);
    if (tid < 16) cpa16(smb + OFF_BSM + tid * 16, (const char*)pre_b + tid * 16);
#pragma unroll
    for (int it = 0; it < 2; it++) {
        int ix = tid + it * 256;    // 512 segs: c = ix>>3, seg = ix&7
        cpa16(smb + OFF_ZSM + ix * 16, zb + (size_t)(ix >> 3) * SPA * 4 + (ix & 7) * 16);
    }
#pragma unroll
    for (int it = 0; it < 8; it++)
        cpa16(smb + OFF_ESM + (tid + it * 256) * 16, (const char*)g_eT + (tid + it * 256) * 16);
    if (tid < 32) cpa16(smb + OFF_E2 + tid * 16, (const char*)g_e2 + tid * 16);
    CP_COMMIT();
#pragma unroll
    for (int it = 0; it < 8; it++)
        cpa16(smb + OFF_ESM + 32768 + (tid + it * 256) * 16,
              (const char*)g_eT + 32768 + (tid + it * 256) * 16);
    if (tid < 32) cpa16(smb + OFF_E2 + 512 + tid * 16, (const char*)(g_e2 + 128) + tid * 16);
    CP_COMMIT();
    CP_WAIT1();                     // group A landed (w, b, z, chunk0)
    __syncthreads();

    // ---- phase 0: pre-conv for this block's 32 tokens -> tsm[c][p]
    {
        float acc8[8];
#pragma unroll
        for (int o8 = 0; o8 < 8; o8++) acc8[o8] = bsm[8 * q + o8];
#pragma unroll 8
        for (int c = 0; c < 64; c++) {
            float zv = zsm[c * 32 + p];
#pragma unroll
            for (int o8 = 0; o8 < 8; o8++)
                acc8[o8] = fmaf(zv, wsm[(8 * q + o8) * 64 + c], acc8[o8]);
        }
#pragma unroll
        for (int o8 = 0; o8 < 8; o8++) tsm[(8 * q + o8) * 32 + p] = acc8[o8];
    }
    __syncthreads();

    // ---- main loop: 32 chunks of 128 codes, exact fp32, double-buffered
    float best = FLT_MAX;
    int bi = 0x7fffffff;

    for (int i = 0; i < 32; i++) {
        if (i < 31) { CP_WAIT1(); } else { CP_WAIT0(); }
        __syncthreads();
        int buf = i & 1;
        const float* eb  = (const float*)(sm + OFF_ESM + buf * 32768);
        const float* e2b = (const float*)(sm + OFF_E2 + buf * 512);
        const float* erow = eb + q * 16;

        ull acc[8];
#pragma unroll
        for (int j = 0; j < 8; j++) acc[j] = 0ull;

#pragma unroll 8
        for (int c = 0; c < 64; c++) {
            float tv = tsm[c * 32 + p];
            ull td = dup2(tv);
            const ulonglong2* ep = (const ulonglong2*)(erow + c * 128);
            ulonglong2 ea = ep[0];          // codes 0..3 of my 16 (warp-uniform LDS)
            ulonglong2 eb2 = ep[1];         // codes 4..7
            const ulonglong2* ep2 = (const ulonglong2*)(erow + c * 128 + 8);
            ulonglong2 ec = ep2[0];         // codes 8..11
            ulonglong2 ed = ep2[1];         // codes 12..15
            acc[0] = ffma2(td, ea.x,  acc[0]);
            acc[1] = ffma2(td, ea.y,  acc[1]);
            acc[2] = ffma2(td, eb2.x, acc[2]);
            acc[3] = ffma2(td, eb2.y, acc[3]);
            acc[4] = ffma2(td, ec.x,  acc[4]);
            acc[5] = ffma2(td, ec.y,  acc[5]);
            acc[6] = ffma2(td, ed.x,  acc[6]);
            acc[7] = ffma2(td, ed.y,  acc[7]);
        }

        // epilogue: score = e2 - 2*dot; strict < ascending k (jnp tie-break)
        int kb = i * 128 + q * 16;
#pragma unroll
        for (int j = 0; j < 8; j++) {
            float e2a = e2b[q * 16 + 2 * j];
            float e2c = e2b[q * 16 + 2 * j + 1];
            float s0v = fmaf(f2lo(acc[j]), -2.0f, e2a);
            float s1v = fmaf(f2hi(acc[j]), -2.0f, e2c);
            if (s0v < best) { best = s0v; bi = kb + 2 * j; }
            if (s1v < best) { best = s1v; bi = kb + 2 * j + 1; }
        }

        __syncthreads();            // all warps done reading buf
        if (i + 2 < 32) {
            const char* es = (const char*)g_eT + (size_t)(i + 2) * 32768;
#pragma unroll
            for (int it = 0; it < 8; it++)
                cpa16(smb + OFF_ESM + buf * 32768 + (tid + it * 256) * 16,
                      es + (tid + it * 256) * 16);
            if (tid < 32)
                cpa16(smb + OFF_E2 + buf * 512 + tid * 16,
                      (const char*)(g_e2 + (i + 2) * 128) + tid * 16);
            CP_COMMIT();
        }
    }

    // ---- cross-warp argmin reduce per token (lowest-index tie-break)
    rv[q * 32 + p] = best;
    ri[q * 32 + p] = bi;
    __syncthreads();
    if (tid < 32) {
        float bv = FLT_MAX;
        int bk = 0x7fffffff;
#pragma unroll
        for (int w = 0; w < 8; w++) {
            float v = rv[w * 32 + tid];
            int k = ri[w * 32 + tid];
            if (v < bv || (v == bv && k < bk)) { bv = v; bk = k; }
        }
        idxs[tid] = bk;
    }
    __syncthreads();

    // ---- fused output epilogue: loss partial + pe gather + idx out
    {
        int myidx = idxs[p];
        const float4* er = (const float4*)(emb + (size_t)myidx * 64 + 8 * q);
        float4 e0 = er[0], e1 = er[1];
        float lp = 0.0f;
        float d;
        d = e0.x - tsm[(8 * q + 0) * 32 + p]; lp = fmaf(d, d, lp);
        d = e0.y - tsm[(8 * q + 1) * 32 + p]; lp = fmaf(d, d, lp);
        d = e0.z - tsm[(8 * q + 2) * 32 + p]; lp = fmaf(d, d, lp);
        d = e0.w - tsm[(8 * q + 3) * 32 + p]; lp = fmaf(d, d, lp);
        d = e1.x - tsm[(8 * q + 4) * 32 + p]; lp = fmaf(d, d, lp);
        d = e1.y - tsm[(8 * q + 5) * 32 + p]; lp = fmaf(d, d, lp);
        d = e1.z - tsm[(8 * q + 6) * 32 + p]; lp = fmaf(d, d, lp);
        d = e1.w - tsm[(8 * q + 7) * 32 + p]; lp = fmaf(d, d, lp);
        lsm[q * 32 + p] = lp;

        const float4* pr = (const float4*)(g_pe + (size_t)myidx * 64 + 8 * q);
        float4 p0 = pr[0], p1 = pr[1];
        float* op = dout + (size_t)b * (CH * SPA) + (size_t)(8 * q) * SPA + s0 + p;
        op[0 * (size_t)SPA] = p0.x;
        op[1 * (size_t)SPA] = p0.y;
        op[2 * (size_t)SPA] = p0.z;
        op[3 * (size_t)SPA] = p0.w;
        op[4 * (size_t)SPA] = p1.x;
        op[5 * (size_t)SPA] = p1.y;
        op[6 * (size_t)SPA] = p1.z;
        op[7 * (size_t)SPA] = p1.w;

        if (q == 0) dout[OUT_ELEMS + 2 + n0 + p] = (float)myidx;
    }
    __syncthreads();
    if (tid < 32) {
        float s = 0.0f;
#pragma unroll
        for (int w = 0; w < 8; w++) s += lsm[w * 32 + tid];
        rv[tid] = s;
    }
    __syncthreads();
    if (tid == 0) {
        float s = 0.0f;
#pragma unroll
        for (int j = 0; j < 32; j++) s += rv[j];
        g_part[blockIdx.x] = s;
    }
}

// ============================================================================
// kD: deterministic final loss reduction over 2048 block partials
// ============================================================================
__global__ void kD(float* __restrict__ dout) {
    __shared__ float red[256];
    int tid = threadIdx.x;
    float s = 0.0f;
#pragma unroll
    for (int j = 0; j < 8; j++) s += g_part[tid + j * 256];
    red[tid] = s;
    __syncthreads();
#pragma unroll
    for (int st = 128; st > 0; st >>= 1) {
        if (tid < st) red[tid] += red[tid + st];
        __syncthreads();
    }
    if (tid == 0) {
        float m = red[0] / (float)OUT_ELEMS;
        dout[OUT_ELEMS]     = m;   // codebook_loss
        dout[OUT_ELEMS + 1] = m;   // commitment_loss (same forward value)
    }
}

// ============================================================================
extern "C" void kernel_launch(void* const* d_in, const int* in_sizes, int n_in,
                              void* d_out, int out_size) {
    const float* z      = (const float*)d_in[0];
    const float* emb    = (const float*)d_in[1];
    const float* pre_w  = (const float*)d_in[2];
    const float* pre_b  = (const float*)d_in[3];
    const float* post_w = (const float*)d_in[4];
    const float* post_b = (const float*)d_in[5];
    float* dout = (float*)d_out;

    cudaFuncSetAttribute(kB, cudaFuncAttributeMaxDynamicSharedMemorySize, SMTOT);

    kP<<<KCODE / 16, 64>>>(emb, post_w, post_b);
    kB<<<NBLK, 256, SMTOT>>>(z, emb, pre_w, pre_b, dout);
    kD<<<1, 256>>>(dout);
}

// round 10
// speedup vs baseline: 3.4210x; 1.3643x over previous
#include <cuda_runtime.h>
#include <cstdint>
#include <cfloat>

// Problem constants: z (2,64,8,64,64), embedding (4096,64)
#define CH 64
#define SPA 32768
#define NTOK 65536
#define KCODE 4096
#define OUT_ELEMS 4194304
#define TBLK 64
#define NBLK (NTOK / TBLK)      // 1024

// kB smem byte offsets (16B aligned)
#define OFF_WSM 0               // pre_w [o][c]                  16384
#define OFF_BSM 16384           // pre_b                           256
#define OFF_ZSM 16640           // z tile [64 c][64 tok]         16384
#define OFF_TSM 33024           // t tile [64 c][64 tok]         16384
#define OFF_ESM 49408           // e chunks 2 x [64 c][128 k]    65536
#define OFF_E2  114944          // e2 2 x 128 f                   1024
#define OFF_RV  115968          // argmin vals [8 w][64 t]        2048
#define OFF_RI  118016          // argmin idxs [8 w][64 t]        2048
#define OFF_IDX 120064          // final idx [64]                  256
#define OFF_LSM 120320          // loss partials [4][64]          1024
#define SMTOT   121344          // > 113.5KB => exactly 1 CTA/SM

typedef unsigned long long ull;

// -------- static device scratch (no cudaMalloc allowed) --------
__device__ __align__(16) float g_eT[KCODE / 128][64][128];   // [chunk][c][k]
__device__ __align__(16) float g_e2[KCODE];
__device__ __align__(16) float g_pe[KCODE * CH];             // emb @ post_w^T + post_b
__device__ float g_part[NBLK];

// -------- helpers (proven R2/R9) --------
__device__ __forceinline__ uint32_t smem_u32(const void* p) {
    uint32_t a;
    asm("{ .reg .u64 t; cvta.to.shared.u64 t, %1; cvt.u32.u64 %0, t; }" : "=r"(a) : "l"(p));
    return a;
}
__device__ __forceinline__ void cpa16(uint32_t dst, const void* src) {
    asm volatile("cp.async.cg.shared.global [%0], [%1], 16;" :: "r"(dst), "l"(src) : "memory");
}
#define CP_COMMIT() asm volatile("cp.async.commit_group;" ::: "memory")
#define CP_WAIT0()  asm volatile("cp.async.wait_group 0;" ::: "memory")
#define CP_WAIT1()  asm volatile("cp.async.wait_group 1;" ::: "memory")

__device__ __forceinline__ ull ffma2(ull a, ull b, ull c) {
    ull d;
    asm("fma.rn.f32x2 %0, %1, %2, %3;" : "=l"(d) : "l"(a), "l"(b), "l"(c));
    return d;
}
__device__ __forceinline__ ull dup2(float x) {
    ull d;
    unsigned u = __float_as_uint(x);
    asm("mov.b64 %0, {%1, %2};" : "=l"(d) : "r"(u), "r"(u));
    return d;
}
__device__ __forceinline__ float f2lo(ull v) { return __uint_as_float((unsigned)v); }
__device__ __forceinline__ float f2hi(ull v) { return __uint_as_float((unsigned)(v >> 32)); }

// ============================================================================
// kP: pe = emb @ post_w^T + post_b ; e2 ; transposed codebook g_eT.
// 256 blocks x 256 thr; 4 codes in parallel (sub-blocks of 64 threads).
// ============================================================================
__global__ void __launch_bounds__(256) kP(const float* __restrict__ emb,
                                          const float* __restrict__ post_w,
                                          const float* __restrict__ post_b) {
    __shared__ float wsm[64 * 65];
    __shared__ float esm[4][64];
    __shared__ float wred[4][2];
    int tid = threadIdx.x;
    int sub = tid >> 6;
    int o = tid & 63;
    int wh = (tid >> 5) & 1;

    for (int i = tid; i < 4096; i += 256)
        wsm[(i >> 6) * 65 + (i & 63)] = post_w[i];
    float wb = post_b[o];

    for (int kk = 0; kk < 4; kk++) {
        int k = blockIdx.x * 16 + kk * 4 + sub;
        __syncthreads();
        float v = emb[k * 64 + o];
        esm[sub][o] = v;
        float sq = v * v;
#pragma unroll
        for (int off = 16; off; off >>= 1)
            sq += __shfl_xor_sync(0xffffffffu, sq, off);
        if ((tid & 31) == 0) wred[sub][wh] = sq;
        __syncthreads();
        float acc = wb;
#pragma unroll
        for (int c = 0; c < 64; c++)
            acc = fmaf(esm[sub][c], wsm[o * 65 + c], acc);
        g_pe[k * 64 + o] = acc;
        g_eT[k >> 7][o][k & 127] = v;
        if (o == 0) g_e2[k] = wred[sub][0] + wred[sub][1];
    }
}

// ============================================================================
// kB: fused pre-conv + exact fp32 FFMA2 argmin + loss/gather/output epilogue.
// 1024 CTAs x 256 thr; 64 tokens/CTA; 1 CTA/SM (smem-forced) -> 7 waves @98.9%.
// Main loop = R2's proven layout: lane tx -> token pair (2tx,2tx+1),
// warp ty -> 16-code stripe; e chunks double-buffered via cp.async.
// ============================================================================
__global__ void __launch_bounds__(256) kB(const float* __restrict__ z,
                                          const float* __restrict__ emb,
                                          const float* __restrict__ pre_w,
                                          const float* __restrict__ pre_b,
                                          float* __restrict__ dout) {
    extern __shared__ __align__(16) char sm[];
    uint32_t smb = smem_u32(sm);
    float* wsm  = (float*)(sm + OFF_WSM);
    float* bsm  = (float*)(sm + OFF_BSM);
    float* zsm  = (float*)(sm + OFF_ZSM);
    float* tsm  = (float*)(sm + OFF_TSM);
    float* rv   = (float*)(sm + OFF_RV);
    int*   ri   = (int*)  (sm + OFF_RI);
    int*   idxs = (int*)  (sm + OFF_IDX);
    float* lsm  = (float*)(sm + OFF_LSM);

    int tid = threadIdx.x;
    int ty = tid >> 5;              // warp: 16-code stripe
    int tx = tid & 31;              // lane: token pair (2tx, 2tx+1)
    int n0 = blockIdx.x * TBLK;
    int b  = n0 >> 15;
    int s0 = n0 & 32767;

    // ---- prologue cp.async: group0 = {w, b, z, e chunk0, e2_0}; group1 = {chunk1, e2_1}
    const char* zb = (const char*)z + ((size_t)b * (CH * SPA) + s0) * 4;
#pragma unroll
    for (int it = 0; it < 4; it++)
        cpa16(smb + OFF_WSM + (tid + it * 256) * 16, (const char*)pre_w + (tid + it * 256) * 16);
    if (tid < 16) cpa16(smb + OFF_BSM + tid * 16, (const char*)pre_b + tid * 16);
#pragma unroll
    for (int it = 0; it < 4; it++) {
        int ix = tid + it * 256;    // 1024 segs: c = ix>>4, seg = ix&15
        cpa16(smb + OFF_ZSM + ix * 16, zb + (size_t)(ix >> 4) * SPA * 4 + (ix & 15) * 16);
    }
#pragma unroll
    for (int it = 0; it < 8; it++)
        cpa16(smb + OFF_ESM + (tid + it * 256) * 16, (const char*)g_eT + (tid + it * 256) * 16);
    if (tid < 32) cpa16(smb + OFF_E2 + tid * 16, (const char*)g_e2 + tid * 16);
    CP_COMMIT();
#pragma unroll
    for (int it = 0; it < 8; it++)
        cpa16(smb + OFF_ESM + 32768 + (tid + it * 256) * 16,
              (const char*)g_eT + 32768 + (tid + it * 256) * 16);
    if (tid < 32) cpa16(smb + OFF_E2 + 512 + tid * 16, (const char*)(g_e2 + 128) + tid * 16);
    CP_COMMIT();
    CP_WAIT1();                     // group0 landed (w, b, z, chunk0, e2_0)
    __syncthreads();

    // ---- phase 0: pre-conv for this block's 64 tokens -> tsm[c][tok]
    {
        int g = tid >> 6;           // 0..3 -> 16 output channels
        int j = tid & 63;           // token
        float acc16[16];
#pragma unroll
        for (int o = 0; o < 16; o++) acc16[o] = bsm[g * 16 + o];
#pragma unroll 8
        for (int c = 0; c < 64; c++) {
            float zv = zsm[c * 64 + j];
#pragma unroll
            for (int o = 0; o < 16; o++)
                acc16[o] = fmaf(zv, wsm[(g * 16 + o) * 64 + c], acc16[o]);
        }
#pragma unroll
        for (int o = 0; o < 16; o++) tsm[(g * 16 + o) * 64 + j] = acc16[o];
    }
    __syncthreads();

    // ---- main loop: 32 chunks of 128 codes, exact fp32, double-buffered
    float best0 = FLT_MAX, best1 = FLT_MAX;
    int bi0 = 0x7fffffff, bi1 = 0x7fffffff;

    for (int i = 0; i < 32; i++) {
        if (i < 31) { CP_WAIT1(); } else { CP_WAIT0(); }
        __syncthreads();
        int buf = i & 1;
        const float* erow = (const float*)(sm + OFF_ESM + buf * 32768) + ty * 16;
        const float* e2b  = (const float*)(sm + OFF_E2 + buf * 512);

        ull acc[2][8];
#pragma unroll
        for (int t = 0; t < 2; t++)
#pragma unroll
            for (int j = 0; j < 8; j++) acc[t][j] = 0ull;

#pragma unroll 8
        for (int c = 0; c < 64; c++) {
            float2 tv = *(const float2*)(tsm + c * 64 + 2 * tx);
            ull td0 = dup2(tv.x);
            ull td1 = dup2(tv.y);
            const ulonglong2* ep = (const ulonglong2*)(erow + c * 128);
            ulonglong2 ea = ep[0];      // codes 0..3 of my 16 (warp-uniform LDS)
            ulonglong2 eb = ep[1];      // codes 4..7
            const ulonglong2* ep2 = (const ulonglong2*)(erow + c * 128 + 8);
            ulonglong2 ec = ep2[0];     // codes 8..11
            ulonglong2 ed = ep2[1];     // codes 12..15
            acc[0][0] = ffma2(td0, ea.x, acc[0][0]);
            acc[1][0] = ffma2(td1, ea.x, acc[1][0]);
            acc[0][1] = ffma2(td0, ea.y, acc[0][1]);
            acc[1][1] = ffma2(td1, ea.y, acc[1][1]);
            acc[0][2] = ffma2(td0, eb.x, acc[0][2]);
            acc[1][2] = ffma2(td1, eb.x, acc[1][2]);
            acc[0][3] = ffma2(td0, eb.y, acc[0][3]);
            acc[1][3] = ffma2(td1, eb.y, acc[1][3]);
            acc[0][4] = ffma2(td0, ec.x, acc[0][4]);
            acc[1][4] = ffma2(td1, ec.x, acc[1][4]);
            acc[0][5] = ffma2(td0, ec.y, acc[0][5]);
            acc[1][5] = ffma2(td1, ec.y, acc[1][5]);
            acc[0][6] = ffma2(td0, ed.x, acc[0][6]);
            acc[1][6] = ffma2(td1, ed.x, acc[1][6]);
            acc[0][7] = ffma2(td0, ed.y, acc[0][7]);
            acc[1][7] = ffma2(td1, ed.y, acc[1][7]);
        }

        // score = e2 - 2*dot ; ascending k, strict < (jnp argmin tie-break)
        int kb = i * 128 + ty * 16;
#pragma unroll
        for (int j = 0; j < 8; j++) {
            float e2a = e2b[ty * 16 + 2 * j];
            float e2c = e2b[ty * 16 + 2 * j + 1];
            float sA0 = fmaf(f2lo(acc[0][j]), -2.0f, e2a);
            float sB0 = fmaf(f2hi(acc[0][j]), -2.0f, e2c);
            float sA1 = fmaf(f2lo(acc[1][j]), -2.0f, e2a);
            float sB1 = fmaf(f2hi(acc[1][j]), -2.0f, e2c);
            if (sA0 < best0) { best0 = sA0; bi0 = kb + 2 * j; }
            if (sB0 < best0) { best0 = sB0; bi0 = kb + 2 * j + 1; }
            if (sA1 < best1) { best1 = sA1; bi1 = kb + 2 * j; }
            if (sB1 < best1) { best1 = sB1; bi1 = kb + 2 * j + 1; }
        }

        __syncthreads();            // all warps done reading buf
        if (i + 2 < 32) {
            const char* es = (const char*)g_eT + (size_t)(i + 2) * 32768;
#pragma unroll
            for (int it = 0; it < 8; it++)
                cpa16(smb + OFF_ESM + buf * 32768 + (tid + it * 256) * 16,
                      es + (tid + it * 256) * 16);
            if (tid < 32)
                cpa16(smb + OFF_E2 + buf * 512 + tid * 16,
                      (const char*)(g_e2 + (i + 2) * 128) + tid * 16);
            CP_COMMIT();
        }
    }

    // ---- cross-warp argmin reduce per token (lowest-index tie-break)
    rv[ty * 64 + 2 * tx]     = best0;
    rv[ty * 64 + 2 * tx + 1] = best1;
    ri[ty * 64 + 2 * tx]     = bi0;
    ri[ty * 64 + 2 * tx + 1] = bi1;
    __syncthreads();
    if (tid < 64) {
        float bv = FLT_MAX;
        int bk = 0x7fffffff;
#pragma unroll
        for (int w = 0; w < 8; w++) {
            float v = rv[w * 64 + tid];
            int k = ri[w * 64 + tid];
            if (v < bv || (v == bv && k < bk)) { bv = v; bk = k; }
        }
        idxs[tid] = bk;
    }
    __syncthreads();

    // ---- fused output epilogue: loss partial + pe gather + idx out
    {
        int g = tid >> 6;           // 16 channels
        int j = tid & 63;           // token
        int myidx = idxs[j];
        const float4* er = (const float4*)(emb + (size_t)myidx * 64 + g * 16);
        const float4* pr = (const float4*)(g_pe + (size_t)myidx * 64 + g * 16);
        float lp = 0.0f;
        float* op = dout + (size_t)b * (CH * SPA) + (size_t)(g * 16) * SPA + s0 + j;
#pragma unroll
        for (int q4 = 0; q4 < 4; q4++) {
            float4 e4 = er[q4];
            float4 p4 = pr[q4];
            int o = q4 * 4;
            float d;
            d = e4.x - tsm[(g * 16 + o + 0) * 64 + j]; lp = fmaf(d, d, lp);
            d = e4.y - tsm[(g * 16 + o + 1) * 64 + j]; lp = fmaf(d, d, lp);
            d = e4.z - tsm[(g * 16 + o + 2) * 64 + j]; lp = fmaf(d, d, lp);
            d = e4.w - tsm[(g * 16 + o + 3) * 64 + j]; lp = fmaf(d, d, lp);
            op[(size_t)(o + 0) * SPA] = p4.x;
            op[(size_t)(o + 1) * SPA] = p4.y;
            op[(size_t)(o + 2) * SPA] = p4.z;
            op[(size_t)(o + 3) * SPA] = p4.w;
        }
        lsm[g * 64 + j] = lp;
        if (g == 0) dout[OUT_ELEMS + 2 + n0 + j] = (float)myidx;
    }
    __syncthreads();
    if (tid < 64) {
        float s = lsm[tid] + lsm[64 + tid] + lsm[128 + tid] + lsm[192 + tid];
        rv[tid] = s;
    }
    __syncthreads();
    if (tid == 0) {
        float s = 0.0f;
#pragma unroll
        for (int j = 0; j < 64; j++) s += rv[j];
        g_part[blockIdx.x] = s;
    }
}

// ============================================================================
// kD: deterministic final loss reduction over 1024 block partials
// ============================================================================
__global__ void kD(float* __restrict__ dout) {
    __shared__ float red[256];
    int tid = threadIdx.x;
    float s = 0.0f;
#pragma unroll
    for (int j = 0; j < 4; j++) s += g_part[tid + j * 256];
    red[tid] = s;
    __syncthreads();
#pragma unroll
    for (int st = 128; st > 0; st >>= 1) {
        if (tid < st) red[tid] += red[tid + st];
        __syncthreads();
    }
    if (tid == 0) {
        float m = red[0] / (float)OUT_ELEMS;
        dout[OUT_ELEMS]     = m;   // codebook_loss
        dout[OUT_ELEMS + 1] = m;   // commitment_loss (same forward value)
    }
}

// ============================================================================
extern "C" void kernel_launch(void* const* d_in, const int* in_sizes, int n_in,
                              void* d_out, int out_size) {
    const float* z      = (const float*)d_in[0];
    const float* emb    = (const float*)d_in[1];
    const float* pre_w  = (const float*)d_in[2];
    const float* pre_b  = (const float*)d_in[3];
    const float* post_w = (const float*)d_in[4];
    const float* post_b = (const float*)d_in[5];
    float* dout = (float*)d_out;

    cudaFuncSetAttribute(kB, cudaFuncAttributeMaxDynamicSharedMemorySize, SMTOT);

    kP<<<KCODE / 16, 256>>>(emb, post_w, post_b);
    kB<<<NBLK, 256, SMTOT>>>(z, emb, pre_w, pre_b, dout);
    kD<<<1, 256>>>(dout);
}